// round 3
// baseline (speedup 1.0000x reference)
#include <cuda_runtime.h>

// Problem constants
#define Bv 2
#define Ev 512
#define Tv 2048
#define Hv 8
#define DHv 64
#define WIN 64          // LOCAL_SIZE/2
#define NEG_INF_F (-1e9f)

// Scratch (allocation-free: __device__ globals)
__device__ float g_qkv[(size_t)Bv * 3 * Ev * Tv];  // [b][3E][t]  ~25 MB
__device__ float g_ctx[(size_t)Bv * Ev * Tv];      // [b][E][t]   ~8 MB

// ---------------------------------------------------------------------------
// GEMM 1: qkv[b][o][t] = sum_e W[o][e] * x[b][e][t] + bias[o]
// M = 3E = 1536, N = T = 2048, K = E = 512.  128x128x16 tile, 8x8/thread.
// ---------------------------------------------------------------------------
__global__ __launch_bounds__(256, 2) void gemm_qkv_kernel(
    const float* __restrict__ x, const float* __restrict__ W,
    const float* __restrict__ bias)
{
    const int M = 3 * Ev, N = Tv, K = Ev;
    __shared__ float As[16][132];   // A^T tile, padded
    __shared__ float Bs[16][128];

    const int b  = blockIdx.z;
    const int m0 = blockIdx.y * 128;
    const int n0 = blockIdx.x * 128;
    const float* Xb = x + (size_t)b * K * N;

    const int tid = threadIdx.x;
    const int irA = tid >> 2, icA = (tid & 3) * 4;   // A: 128 rows x 16 cols
    const int irB = tid >> 5, icB = (tid & 31) * 4;  // B: 16 rows x 128 cols
    const int tx = tid & 15, ty = tid >> 4;

    float acc[8][8] = {};

    for (int k0 = 0; k0 < K; k0 += 16) {
#pragma unroll
        for (int ro = 0; ro < 128; ro += 64) {
            float4 a = *(const float4*)&W[(size_t)(m0 + irA + ro) * K + k0 + icA];
            As[icA + 0][irA + ro] = a.x;
            As[icA + 1][irA + ro] = a.y;
            As[icA + 2][irA + ro] = a.z;
            As[icA + 3][irA + ro] = a.w;
        }
#pragma unroll
        for (int ro = 0; ro < 16; ro += 8) {
            *(float4*)&Bs[irB + ro][icB] =
                *(const float4*)&Xb[(size_t)(k0 + irB + ro) * N + n0 + icB];
        }
        __syncthreads();
#pragma unroll
        for (int kk = 0; kk < 16; kk++) {
            float rm[8], rn[8];
            *(float4*)&rm[0] = *(const float4*)&As[kk][ty * 8];
            *(float4*)&rm[4] = *(const float4*)&As[kk][ty * 8 + 4];
            *(float4*)&rn[0] = *(const float4*)&Bs[kk][tx * 8];
            *(float4*)&rn[4] = *(const float4*)&Bs[kk][tx * 8 + 4];
#pragma unroll
            for (int i = 0; i < 8; i++)
#pragma unroll
                for (int j = 0; j < 8; j++)
                    acc[i][j] += rm[i] * rn[j];
        }
        __syncthreads();
    }

    float* C = g_qkv + (size_t)b * M * N;
#pragma unroll
    for (int i = 0; i < 8; i++) {
        int m = m0 + ty * 8 + i;
        float bv = bias[m];
#pragma unroll
        for (int j = 0; j < 8; j += 4) {
            float4 v;
            v.x = acc[i][j + 0] + bv;
            v.y = acc[i][j + 1] + bv;
            v.z = acc[i][j + 2] + bv;
            v.w = acc[i][j + 3] + bv;
            *(float4*)&C[(size_t)m * N + n0 + tx * 8 + j] = v;
        }
    }
}

// ---------------------------------------------------------------------------
// Sliding-window attention.
// Block = (b, h, 64-query tile). Keys needed: [t0-64, t0+127] -> 192 rows.
// SMEM: Qs[64][65], Ks[192][65], Vs[192][65], S[64][192]  (~166 KB)
// ---------------------------------------------------------------------------
#define ATTN_SMEM ((64 * 65 + 192 * 65 + 192 * 65 + 64 * 192) * 4)

__global__ __launch_bounds__(256, 1) void attn_kernel()
{
    const int t0 = blockIdx.x * 64;
    const int h  = blockIdx.y;
    const int b  = blockIdx.z;

    extern __shared__ float sm[];
    float* Qs = sm;                   // [64][65]
    float* Ks = Qs + 64 * 65;         // [192][65]
    float* Vs = Ks + 192 * 65;        // [192][65]
    float* S  = Vs + 192 * 65;        // [64][192]

    const int tid = threadIdx.x;
    const float* qbase = g_qkv + (size_t)b * 3 * Ev * Tv + (size_t)(h * DHv) * Tv;
    const float* kbase = qbase + (size_t)Ev * Tv;
    const float* vbase = qbase + (size_t)2 * Ev * Tv;

    // Stage Q (transpose feature-major -> [t][d])
    for (int idx = tid; idx < 64 * 64; idx += 256) {
        int d = idx >> 6, r = idx & 63;
        Qs[r * 65 + d] = qbase[(size_t)d * Tv + t0 + r];
    }
    // Stage K, V (192 token rows, zero-fill out of range)
    for (int idx = tid; idx < 192 * 64; idx += 256) {
        int d = idx / 192, r = idx % 192;
        int t = t0 - WIN + r;
        float kv = 0.f, vv = 0.f;
        if (t >= 0 && t < Tv) {
            kv = kbase[(size_t)d * Tv + t];
            vv = vbase[(size_t)d * Tv + t];
        }
        Ks[r * 65 + d] = kv;
        Vs[r * 65 + d] = vv;
    }
    __syncthreads();

    const int tx = tid & 15, ty = tid >> 4;

    // S = Q @ K^T * scale + mask   (64 x 192)
    {
        float acc[4][12] = {};
#pragma unroll
        for (int kk = 0; kk < 64; kk++) {
            float rq[4], rk[12];
#pragma unroll
            for (int i = 0; i < 4; i++) rq[i] = Qs[(ty * 4 + i) * 65 + kk];
#pragma unroll
            for (int j = 0; j < 12; j++) rk[j] = Ks[(tx + j * 16) * 65 + kk];
#pragma unroll
            for (int i = 0; i < 4; i++)
#pragma unroll
                for (int j = 0; j < 12; j++)
                    acc[i][j] += rq[i] * rk[j];
        }
        const float scale = 0.125f;  // 1/sqrt(64)
#pragma unroll
        for (int i = 0; i < 4; i++) {
            int r = ty * 4 + i;
#pragma unroll
            for (int j = 0; j < 12; j++) {
                int c   = tx + j * 16;
                int gk  = t0 - WIN + c;
                int rel = r + WIN - c;                       // gq - gk
                bool valid = (rel >= -WIN) && (rel <= WIN) && (gk >= 0) && (gk < Tv);
                S[r * 192 + c] = valid ? acc[i][j] * scale : NEG_INF_F;
            }
        }
    }
    __syncthreads();

    // Row softmax: warp w handles rows [w*8, w*8+8)
    {
        int warp = tid >> 5, lane = tid & 31;
        for (int rr = 0; rr < 8; rr++) {
            int row = warp * 8 + rr;
            float v[6];
            float mx = -1e30f;
#pragma unroll
            for (int p = 0; p < 6; p++) {
                v[p] = S[row * 192 + lane + p * 32];
                mx = fmaxf(mx, v[p]);
            }
#pragma unroll
            for (int off = 16; off > 0; off >>= 1)
                mx = fmaxf(mx, __shfl_xor_sync(0xFFFFFFFFu, mx, off));
            float sum = 0.f;
#pragma unroll
            for (int p = 0; p < 6; p++) {
                v[p] = __expf(v[p] - mx);
                sum += v[p];
            }
#pragma unroll
            for (int off = 16; off > 0; off >>= 1)
                sum += __shfl_xor_sync(0xFFFFFFFFu, sum, off);
            float inv = 1.f / sum;
#pragma unroll
            for (int p = 0; p < 6; p++)
                S[row * 192 + lane + p * 32] = v[p] * inv;
        }
    }
    __syncthreads();

    // ctx = S @ V   (64 x 64), 4x4 per thread
    float acc2[4][4] = {};
    for (int kk = 0; kk < 192; kk++) {
        float rs[4], rv[4];
#pragma unroll
        for (int i = 0; i < 4; i++) rs[i] = S[(ty * 4 + i) * 192 + kk];
#pragma unroll
        for (int j = 0; j < 4; j++) rv[j] = Vs[kk * 65 + tx * 4 + j];
#pragma unroll
        for (int i = 0; i < 4; i++)
#pragma unroll
            for (int j = 0; j < 4; j++)
                acc2[i][j] += rs[i] * rv[j];
    }
    __syncthreads();

    // Stage ctx^T into SMEM (reuse S): Cs[d][t_local], then coalesced global write
#pragma unroll
    for (int i = 0; i < 4; i++)
#pragma unroll
        for (int j = 0; j < 4; j++)
            S[(tx * 4 + j) * 65 + (ty * 4 + i)] = acc2[i][j];
    __syncthreads();

    float* cbase = g_ctx + (size_t)b * Ev * Tv + (size_t)(h * DHv) * Tv;
    for (int idx = tid; idx < 64 * 64; idx += 256) {
        int d = idx >> 6, r = idx & 63;
        cbase[(size_t)d * Tv + t0 + r] = S[d * 65 + r];
    }
}

// ---------------------------------------------------------------------------
// GEMM 3: out[b][e][t] = relu( (sum_f out_w[e][f]*ctx[b][f][t] + out_b[e]) * x[b][e][t] )
// M = E = 512, N = T = 2048, K = E = 512
// ---------------------------------------------------------------------------
__global__ __launch_bounds__(256, 2) void gemm_out_kernel(
    const float* __restrict__ x, const float* __restrict__ W,
    const float* __restrict__ bias, float* __restrict__ out)
{
    const int M = Ev, N = Tv, K = Ev;
    __shared__ float As[16][132];
    __shared__ float Bs[16][128];

    const int b  = blockIdx.z;
    const int m0 = blockIdx.y * 128;
    const int n0 = blockIdx.x * 128;
    const float* Cb = g_ctx + (size_t)b * K * N;

    const int tid = threadIdx.x;
    const int irA = tid >> 2, icA = (tid & 3) * 4;
    const int irB = tid >> 5, icB = (tid & 31) * 4;
    const int tx = tid & 15, ty = tid >> 4;

    float acc[8][8] = {};

    for (int k0 = 0; k0 < K; k0 += 16) {
#pragma unroll
        for (int ro = 0; ro < 128; ro += 64) {
            float4 a = *(const float4*)&W[(size_t)(m0 + irA + ro) * K + k0 + icA];
            As[icA + 0][irA + ro] = a.x;
            As[icA + 1][irA + ro] = a.y;
            As[icA + 2][irA + ro] = a.z;
            As[icA + 3][irA + ro] = a.w;
        }
#pragma unroll
        for (int ro = 0; ro < 16; ro += 8) {
            *(float4*)&Bs[irB + ro][icB] =
                *(const float4*)&Cb[(size_t)(k0 + irB + ro) * N + n0 + icB];
        }
        __syncthreads();
#pragma unroll
        for (int kk = 0; kk < 16; kk++) {
            float rm[8], rn[8];
            *(float4*)&rm[0] = *(const float4*)&As[kk][ty * 8];
            *(float4*)&rm[4] = *(const float4*)&As[kk][ty * 8 + 4];
            *(float4*)&rn[0] = *(const float4*)&Bs[kk][tx * 8];
            *(float4*)&rn[4] = *(const float4*)&Bs[kk][tx * 8 + 4];
#pragma unroll
            for (int i = 0; i < 8; i++)
#pragma unroll
                for (int j = 0; j < 8; j++)
                    acc[i][j] += rm[i] * rn[j];
        }
        __syncthreads();
    }

    const float* Xb = x + (size_t)b * M * N;
    float* Ob = out + (size_t)b * M * N;
#pragma unroll
    for (int i = 0; i < 8; i++) {
        int m = m0 + ty * 8 + i;
        float bv = bias[m];
        size_t rowoff = (size_t)m * N + n0 + tx * 8;
#pragma unroll
        for (int j = 0; j < 8; j += 4) {
            float4 xv = *(const float4*)&Xb[rowoff + j];
            float4 v;
            v.x = fmaxf(0.f, (acc[i][j + 0] + bv) * xv.x);
            v.y = fmaxf(0.f, (acc[i][j + 1] + bv) * xv.y);
            v.z = fmaxf(0.f, (acc[i][j + 2] + bv) * xv.z);
            v.w = fmaxf(0.f, (acc[i][j + 3] + bv) * xv.w);
            *(float4*)&Ob[rowoff + j] = v;
        }
    }
}

// ---------------------------------------------------------------------------
extern "C" void kernel_launch(void* const* d_in, const int* in_sizes, int n_in,
                              void* d_out, int out_size)
{
    const float* x     = (const float*)d_in[0];  // [B, E, T]
    const float* w_in  = (const float*)d_in[1];  // [3E, E]
    const float* b_in  = (const float*)d_in[2];  // [3E]
    const float* w_out = (const float*)d_in[3];  // [E, E]
    const float* b_out = (const float*)d_in[4];  // [E]
    float* out = (float*)d_out;                  // [B, E, T]

    cudaFuncSetAttribute(attn_kernel,
                         cudaFuncAttributeMaxDynamicSharedMemorySize, ATTN_SMEM);

    dim3 g1(Tv / 128, (3 * Ev) / 128, Bv);       // 16 x 12 x 2
    gemm_qkv_kernel<<<g1, 256>>>(x, w_in, b_in);

    dim3 g2(Tv / 64, Hv, Bv);                    // 32 x 8 x 2
    attn_kernel<<<g2, 256, ATTN_SMEM>>>();

    dim3 g3(Tv / 128, Ev / 128, Bv);             // 16 x 4 x 2
    gemm_out_kernel<<<g3, 256>>>(x, w_out, b_out, out);
}

// round 6
// speedup vs baseline: 1.3145x; 1.3145x over previous
#include <cuda_runtime.h>
#include <cstdint>

// Problem constants
#define Bv 2
#define Ev 512
#define Tv 2048
#define Hv 8
#define DHv 64
#define WIN 64
#define NEG_INF_F (-1e9f)

// Scratch (allocation-free: __device__ globals)
__device__ float g_qkv[(size_t)Bv * 3 * Ev * Tv];  // [b][3E][t]
__device__ float g_ctx[(size_t)Bv * Ev * Tv];      // [b][E][t]

// ---------------------------------------------------------------------------
// TF32 helpers
// ---------------------------------------------------------------------------
__device__ __forceinline__ uint32_t f2tf32(float x) {
    uint32_t r;
    asm("cvt.rna.tf32.f32 %0, %1;" : "=r"(r) : "f"(x));
    return r;
}

__device__ __forceinline__ void mma_tf32(float c[4],
    uint32_t a0, uint32_t a1, uint32_t a2, uint32_t a3,
    uint32_t b0, uint32_t b1)
{
    asm volatile(
        "mma.sync.aligned.m16n8k8.row.col.f32.tf32.tf32.f32 "
        "{%0,%1,%2,%3}, {%4,%5,%6,%7}, {%8,%9}, {%0,%1,%2,%3};"
        : "+f"(c[0]), "+f"(c[1]), "+f"(c[2]), "+f"(c[3])
        : "r"(a0), "r"(a1), "r"(a2), "r"(a3), "r"(b0), "r"(b1));
}

// ---------------------------------------------------------------------------
// Tensor-core GEMM (3xTF32): C[b][m][n] = sum_k W[m][k] * Bmat[b][k][n] + bias[m]
// Block 128x128, K-tile 16, 8 warps (2x4), warp tile 64x32, m16n8k8 frags.
// SMEM: double-buffered {Ah, Al, Bh, Bl}, each 16 rows x stride 136.
// FUSE epilogue: out = relu((C + bias) * x)
// ---------------------------------------------------------------------------
#define KT 16
#define LDT 136
#define STAGE (KT * LDT)            // 2176 floats per plane
#define GEMM_SMEM (2 * 4 * STAGE * 4)  // 69632 bytes

template<bool FUSE>
__global__ __launch_bounds__(256) void gemm_tc(
    const float* __restrict__ Bmat,   // [B][K][N]
    const float* __restrict__ W,      // [M][K]
    const float* __restrict__ bias,   // [M]
    const float* __restrict__ xep,    // [B][M][N] (FUSE only)
    float* __restrict__ Cout,         // [B][M][N]
    int M)
{
    const int N = Tv, K = Ev;
    extern __shared__ float sm[];

    const int b  = blockIdx.z;
    const int m0 = blockIdx.y * 128;
    const int n0 = blockIdx.x * 128;
    const float* Bb = Bmat + (size_t)b * K * N;

    const int tid  = threadIdx.x;
    const int lane = tid & 31;
    const int warp = tid >> 5;
    const int wm = (warp >> 2) * 64;
    const int wn = (warp & 3) * 32;
    const int g  = lane >> 2;
    const int tig = lane & 3;

    const int irA = tid >> 2, icA = (tid & 3) * 4;   // A tile: 128 rows, 16 k
    const int irB = tid >> 5, icB = (tid & 31) * 4;  // B tile: 16 k, 128 n

    float4 ra[2], rb[2];

    // global loads for k-tile k0 into registers
    auto gload = [&](int k0) {
        ra[0] = *(const float4*)&W[(size_t)(m0 + irA) * K + k0 + icA];
        ra[1] = *(const float4*)&W[(size_t)(m0 + irA + 64) * K + k0 + icA];
        rb[0] = *(const float4*)&Bb[(size_t)(k0 + irB) * N + n0 + icB];
        rb[1] = *(const float4*)&Bb[(size_t)(k0 + irB + 8) * N + n0 + icB];
    };

    // convert + store registers into smem buffer
    auto stage = [&](int buf) {
        float* Ah = sm + buf * 4 * STAGE;
        float* Al = Ah + STAGE;
        float* Bh = Al + STAGE;
        float* Bl = Bh + STAGE;
#pragma unroll
        for (int h = 0; h < 2; h++) {
            float av[4] = { (h ? ra[1].x : ra[0].x), (h ? ra[1].y : ra[0].y),
                            (h ? ra[1].z : ra[0].z), (h ? ra[1].w : ra[0].w) };
            int m = irA + h * 64;
#pragma unroll
            for (int j = 0; j < 4; j++) {
                uint32_t hi = f2tf32(av[j]);
                float hif = __uint_as_float(hi);
                uint32_t lo = f2tf32(av[j] - hif);
                Ah[(icA + j) * LDT + m] = hif;
                Al[(icA + j) * LDT + m] = __uint_as_float(lo);
            }
        }
#pragma unroll
        for (int h = 0; h < 2; h++) {
            float bv[4] = { (h ? rb[1].x : rb[0].x), (h ? rb[1].y : rb[0].y),
                            (h ? rb[1].z : rb[0].z), (h ? rb[1].w : rb[0].w) };
            float hi4[4], lo4[4];
#pragma unroll
            for (int j = 0; j < 4; j++) {
                uint32_t hi = f2tf32(bv[j]);
                hi4[j] = __uint_as_float(hi);
                lo4[j] = __uint_as_float(f2tf32(bv[j] - hi4[j]));
            }
            int kr = irB + h * 8;
            *(float4*)&Bh[kr * LDT + icB] = make_float4(hi4[0], hi4[1], hi4[2], hi4[3]);
            *(float4*)&Bl[kr * LDT + icB] = make_float4(lo4[0], lo4[1], lo4[2], lo4[3]);
        }
    };

    float acc[4][4][4] = {};

    gload(0);
    stage(0);
    __syncthreads();

    const int NIT = K / KT;   // 32
    for (int it = 0; it < NIT; ++it) {
        if (it + 1 < NIT) gload((it + 1) * KT);

        const float* base = sm + (it & 1) * 4 * STAGE;
        const float* Ah = base;
        const float* Al = base + STAGE;
        const float* Bh = base + 2 * STAGE;
        const float* Bl = base + 3 * STAGE;

#pragma unroll
        for (int ks = 0; ks < KT; ks += 8) {
            const int r0 = (ks + tig) * LDT;
            const int r1 = (ks + tig + 4) * LDT;
            uint32_t ah[4][4], al[4][4];
#pragma unroll
            for (int mf = 0; mf < 4; mf++) {
                int m = wm + mf * 16 + g;
                ah[mf][0] = __float_as_uint(Ah[r0 + m]);
                ah[mf][1] = __float_as_uint(Ah[r0 + m + 8]);
                ah[mf][2] = __float_as_uint(Ah[r1 + m]);
                ah[mf][3] = __float_as_uint(Ah[r1 + m + 8]);
                al[mf][0] = __float_as_uint(Al[r0 + m]);
                al[mf][1] = __float_as_uint(Al[r0 + m + 8]);
                al[mf][2] = __float_as_uint(Al[r1 + m]);
                al[mf][3] = __float_as_uint(Al[r1 + m + 8]);
            }
#pragma unroll
            for (int nf = 0; nf < 4; nf++) {
                int n = wn + nf * 8 + g;
                uint32_t bh0 = __float_as_uint(Bh[r0 + n]);
                uint32_t bh1 = __float_as_uint(Bh[r1 + n]);
                uint32_t bl0 = __float_as_uint(Bl[r0 + n]);
                uint32_t bl1 = __float_as_uint(Bl[r1 + n]);
#pragma unroll
                for (int mf = 0; mf < 4; mf++) {
                    mma_tf32(acc[mf][nf], ah[mf][0], ah[mf][1], ah[mf][2], ah[mf][3], bh0, bh1);
                    mma_tf32(acc[mf][nf], ah[mf][0], ah[mf][1], ah[mf][2], ah[mf][3], bl0, bl1);
                    mma_tf32(acc[mf][nf], al[mf][0], al[mf][1], al[mf][2], al[mf][3], bh0, bh1);
                }
            }
        }

        if (it + 1 < NIT) stage((it + 1) & 1);
        __syncthreads();
    }

    // Epilogue
    const float* Xb = xep + (size_t)b * M * N;   // only deref'd when FUSE
    float* Cb = Cout + (size_t)b * M * N;
#pragma unroll
    for (int mf = 0; mf < 4; mf++) {
        int m = m0 + wm + mf * 16 + g;
        float bv0 = bias[m];
        float bv1 = bias[m + 8];
#pragma unroll
        for (int nf = 0; nf < 4; nf++) {
            int n = n0 + wn + nf * 8 + 2 * tig;
            float2 v0 = make_float2(acc[mf][nf][0] + bv0, acc[mf][nf][1] + bv0);
            float2 v1 = make_float2(acc[mf][nf][2] + bv1, acc[mf][nf][3] + bv1);
            if (FUSE) {
                float2 x0 = *(const float2*)&Xb[(size_t)m * N + n];
                float2 x1 = *(const float2*)&Xb[(size_t)(m + 8) * N + n];
                v0.x = fmaxf(0.f, v0.x * x0.x); v0.y = fmaxf(0.f, v0.y * x0.y);
                v1.x = fmaxf(0.f, v1.x * x1.x); v1.y = fmaxf(0.f, v1.y * x1.y);
            }
            *(float2*)&Cb[(size_t)m * N + n] = v0;
            *(float2*)&Cb[(size_t)(m + 8) * N + n] = v1;
        }
    }
}

// ---------------------------------------------------------------------------
// Sliding-window attention, 32-query tiles, 160-key band, V phase-staged
// into K's buffer. SMEM = 70.4 KB -> 3 CTAs/SM.
// ---------------------------------------------------------------------------
#define ATT_SMEM ((32 * 65 + 160 * 65 + 32 * 160) * 4)   // 70400 B

__global__ __launch_bounds__(256) void attn_kernel()
{
    const int t0 = blockIdx.x * 32;
    const int h  = blockIdx.y;
    const int b  = blockIdx.z;

    extern __shared__ float sm[];
    float* Qs = sm;                 // [32][65]
    float* Ks = Qs + 32 * 65;       // [160][65]   (later reused for V)
    float* S  = Ks + 160 * 65;      // [32][160]   (later reused for ctx^T)

    const int tid = threadIdx.x;
    const float* qbase = g_qkv + ((size_t)b * 3 * Ev + h * DHv) * Tv;
    const float* kbase = qbase + (size_t)Ev * Tv;
    const float* vbase = qbase + (size_t)2 * Ev * Tv;

    // Stage Q (transpose feature-major -> [t][d])
    for (int idx = tid; idx < 32 * 64; idx += 256) {
        int d = idx >> 5, r = idx & 31;
        Qs[r * 65 + d] = qbase[(size_t)d * Tv + t0 + r];
    }
    // Stage K (160 token rows centered on tile, zero-fill OOB)
    for (int idx = tid; idx < 160 * 64; idx += 256) {
        int d = idx / 160, r = idx - d * 160;
        int t = t0 - WIN + r;
        Ks[r * 65 + d] = (t >= 0 && t < Tv) ? kbase[(size_t)d * Tv + t] : 0.f;
    }
    __syncthreads();

    const int tx = tid & 31;   // lane
    const int ty = tid >> 5;   // warp

    // S = Q @ K^T * scale + mask   (32 x 160); thread: 4 rows x 5 cols
    {
        float acc[4][5] = {};
#pragma unroll
        for (int kk = 0; kk < 64; kk++) {
            float rq[4], rk[5];
#pragma unroll
            for (int i = 0; i < 4; i++) rq[i] = Qs[(ty * 4 + i) * 65 + kk];
#pragma unroll
            for (int j = 0; j < 5; j++) rk[j] = Ks[(tx + j * 32) * 65 + kk];
#pragma unroll
            for (int i = 0; i < 4; i++)
#pragma unroll
                for (int j = 0; j < 5; j++)
                    acc[i][j] += rq[i] * rk[j];
        }
        const float scale = 0.125f;
#pragma unroll
        for (int i = 0; i < 4; i++) {
            int r = ty * 4 + i;
#pragma unroll
            for (int j = 0; j < 5; j++) {
                int c   = tx + j * 32;
                int gk  = t0 - WIN + c;
                int rel = r + WIN - c;              // gq - gk
                bool valid = (rel >= -WIN) && (rel <= WIN) && (gk >= 0) && (gk < Tv);
                S[r * 160 + c] = valid ? acc[i][j] * scale : NEG_INF_F;
            }
        }
    }
    __syncthreads();

    // Row softmax: warp ty handles rows [ty*4, ty*4+4)
    for (int rr = 0; rr < 4; rr++) {
        int row = ty * 4 + rr;
        float v[5];
        float mx = -1e30f;
#pragma unroll
        for (int p = 0; p < 5; p++) {
            v[p] = S[row * 160 + tx + p * 32];
            mx = fmaxf(mx, v[p]);
        }
#pragma unroll
        for (int off = 16; off > 0; off >>= 1)
            mx = fmaxf(mx, __shfl_xor_sync(0xFFFFFFFFu, mx, off));
        float sum = 0.f;
#pragma unroll
        for (int p = 0; p < 5; p++) {
            v[p] = __expf(v[p] - mx);
            sum += v[p];
        }
#pragma unroll
        for (int off = 16; off > 0; off >>= 1)
            sum += __shfl_xor_sync(0xFFFFFFFFu, sum, off);
        float inv = 1.f / sum;
#pragma unroll
        for (int p = 0; p < 5; p++)
            S[row * 160 + tx + p * 32] = v[p] * inv;
    }
    __syncthreads();

    // Restage V into K's buffer
    for (int idx = tid; idx < 160 * 64; idx += 256) {
        int d = idx / 160, r = idx - d * 160;
        int t = t0 - WIN + r;
        Ks[r * 65 + d] = (t >= 0 && t < Tv) ? vbase[(size_t)d * Tv + t] : 0.f;
    }
    __syncthreads();

    // ctx = S @ V  (32 x 64); thread: 4 rows x 2 cols
    float acc2[4][2] = {};
    for (int kk = 0; kk < 160; kk++) {
        float rs[4], rv[2];
#pragma unroll
        for (int i = 0; i < 4; i++) rs[i] = S[(ty * 4 + i) * 160 + kk];
#pragma unroll
        for (int j = 0; j < 2; j++) rv[j] = Ks[kk * 65 + tx + j * 32];
#pragma unroll
        for (int i = 0; i < 4; i++)
#pragma unroll
            for (int j = 0; j < 2; j++)
                acc2[i][j] += rs[i] * rv[j];
    }
    __syncthreads();

    // Transpose ctx into S region (stride 33), then coalesced write
#pragma unroll
    for (int i = 0; i < 4; i++)
#pragma unroll
        for (int j = 0; j < 2; j++)
            S[(tx + j * 32) * 33 + (ty * 4 + i)] = acc2[i][j];
    __syncthreads();

    float* cbase = g_ctx + ((size_t)b * Ev + h * DHv) * Tv;
    for (int idx = tid; idx < 64 * 32; idx += 256) {
        int d = idx >> 5, r = idx & 31;
        cbase[(size_t)d * Tv + t0 + r] = S[d * 33 + r];
    }
}

// ---------------------------------------------------------------------------
extern "C" void kernel_launch(void* const* d_in, const int* in_sizes, int n_in,
                              void* d_out, int out_size)
{
    const float* x     = (const float*)d_in[0];  // [B, E, T]
    const float* w_in  = (const float*)d_in[1];  // [3E, E]
    const float* b_in  = (const float*)d_in[2];  // [3E]
    const float* w_out = (const float*)d_in[3];  // [E, E]
    const float* b_out = (const float*)d_in[4];  // [E]
    float* out = (float*)d_out;                  // [B, E, T]

    void* qkvp = nullptr;
    void* ctxp = nullptr;
    cudaGetSymbolAddress(&qkvp, g_qkv);
    cudaGetSymbolAddress(&ctxp, g_ctx);

    cudaFuncSetAttribute(gemm_tc<false>,
                         cudaFuncAttributeMaxDynamicSharedMemorySize, GEMM_SMEM);
    cudaFuncSetAttribute(gemm_tc<true>,
                         cudaFuncAttributeMaxDynamicSharedMemorySize, GEMM_SMEM);
    cudaFuncSetAttribute(attn_kernel,
                         cudaFuncAttributeMaxDynamicSharedMemorySize, ATT_SMEM);

    // QKV projection: M=1536
    dim3 g1(Tv / 128, (3 * Ev) / 128, Bv);
    gemm_tc<false><<<g1, 256, GEMM_SMEM>>>(x, w_in, b_in, nullptr,
                                           (float*)qkvp, 3 * Ev);

    // Attention
    dim3 g2(Tv / 32, Hv, Bv);
    attn_kernel<<<g2, 256, ATT_SMEM>>>();

    // Output projection + fused epilogue: M=512
    dim3 g3(Tv / 128, Ev / 128, Bv);
    gemm_tc<true><<<g3, 256, GEMM_SMEM>>>((const float*)ctxp, w_out, b_out, x,
                                          out, Ev);
}

// round 7
// speedup vs baseline: 1.3840x; 1.0528x over previous
#include <cuda_runtime.h>
#include <cstdint>

// Problem constants
#define Bv 2
#define Ev 512
#define Tv 2048
#define Hv 8
#define DHv 64
#define WIN 64
#define NEG_INF_F (-1e9f)

// Scratch (allocation-free: __device__ globals)
__device__ float g_qkv[(size_t)Bv * 3 * Ev * Tv];  // [b][3E][t]
__device__ float g_ctx[(size_t)Bv * Ev * Tv];      // [b][E][t]
// Pre-split TF32 hi/lo planes for both weight matrices.
// [0 .. 1536*512) = W_in, [1536*512 .. +512*512) = W_out
#define WIN_ELEMS (3 * Ev * Ev)
#define WOUT_ELEMS (Ev * Ev)
__device__ float g_wh[WIN_ELEMS + WOUT_ELEMS];
__device__ float g_wl[WIN_ELEMS + WOUT_ELEMS];

// ---------------------------------------------------------------------------
// TF32 helpers
// ---------------------------------------------------------------------------
__device__ __forceinline__ uint32_t f2tf32(float x) {
    uint32_t r;
    asm("cvt.rna.tf32.f32 %0, %1;" : "=r"(r) : "f"(x));
    return r;
}

__device__ __forceinline__ void mma_tf32(float c[4],
    uint32_t a0, uint32_t a1, uint32_t a2, uint32_t a3,
    uint32_t b0, uint32_t b1)
{
    asm volatile(
        "mma.sync.aligned.m16n8k8.row.col.f32.tf32.tf32.f32 "
        "{%0,%1,%2,%3}, {%4,%5,%6,%7}, {%8,%9}, {%0,%1,%2,%3};"
        : "+f"(c[0]), "+f"(c[1]), "+f"(c[2]), "+f"(c[3])
        : "r"(a0), "r"(a1), "r"(a2), "r"(a3), "r"(b0), "r"(b1));
}

__device__ __forceinline__ void cpasync16(uint32_t dst, const void* src) {
    asm volatile("cp.async.cg.shared.global [%0], [%1], 16;\n"
                 :: "r"(dst), "l"(src) : "memory");
}
template<int N>
__device__ __forceinline__ void cp_wait() {
    asm volatile("cp.async.wait_group %0;\n" :: "n"(N) : "memory");
}
__device__ __forceinline__ void cp_commit() {
    asm volatile("cp.async.commit_group;\n" ::: "memory");
}

// ---------------------------------------------------------------------------
// Weight split prep: Wh = tf32(W), Wl = tf32(W - Wh)
// ---------------------------------------------------------------------------
__global__ void split_w_kernel(const float* __restrict__ W,
                               float* __restrict__ Wh, float* __restrict__ Wl,
                               int n)
{
    int i = blockIdx.x * 256 + threadIdx.x;
    if (i < n) {
        float w = W[i];
        uint32_t hi = f2tf32(w);
        float hif = __uint_as_float(hi);
        Wh[i] = hif;
        Wl[i] = __uint_as_float(f2tf32(w - hif));
    }
}

// ---------------------------------------------------------------------------
// Tensor-core GEMM (3xTF32): C[b][m][n] = sum_k W[m][k] * Bmat[b][k][n] + bias
// Block 128x128, K-tile 16, 8 warps (2x4), warp tile 64x32, m16n8k8 frags.
// A pre-split hi/lo planes (m-major, stride 20), B raw f32 (k-major, stride
// 136, split at fragment load). cp.async double-buffered.
// FUSE epilogue: out = relu((C + bias) * x)
// ---------------------------------------------------------------------------
#define KT 16
#define A_PLANE 2560                 // 128 rows * 20 floats
#define A_STRIDE 20
#define B_PLANE 2176                 // 16 rows * 136 floats
#define B_STRIDE 136
#define STAGE_F (2 * A_PLANE + B_PLANE)       // 7296 floats
#define STAGE_B (STAGE_F * 4)                 // 29184 bytes
#define GEMM_SMEM (2 * STAGE_B)               // 58368 bytes

template<bool FUSE>
__global__ __launch_bounds__(256, 2) void gemm_tc(
    const float* __restrict__ Bmat,   // [B][K][N]
    const float* __restrict__ Wh,     // [M][K] tf32-hi
    const float* __restrict__ Wl,     // [M][K] tf32-lo
    const float* __restrict__ bias,   // [M]
    const float* __restrict__ xep,    // [B][M][N] (FUSE only)
    float* __restrict__ Cout,         // [B][M][N]
    int M)
{
    const int N = Tv, K = Ev;
    extern __shared__ float sm[];
    const uint32_t smem_base = (uint32_t)__cvta_generic_to_shared(sm);

    const int b  = blockIdx.z;
    const int m0 = blockIdx.y * 128;
    const int n0 = blockIdx.x * 128;
    const float* Bb = Bmat + (size_t)b * K * N;

    const int tid  = threadIdx.x;
    const int lane = tid & 31;
    const int warp = tid >> 5;
    const int wm = (warp >> 2) * 64;
    const int wn = (warp & 3) * 32;
    const int g  = lane >> 2;
    const int tig = lane & 3;

    // cp.async issue for k-tile k0 into buffer buf
    auto issue = [&](int k0, int buf) {
        uint32_t base = smem_base + buf * STAGE_B;
        // A hi/lo planes: 512 chunks each (128 m x 4 chunks of 4 k)
#pragma unroll
        for (int i = 0; i < 2; i++) {
            int c = tid + i * 256;
            int m = c >> 2, kc = c & 3;
            const float* srcH = Wh + (size_t)(m0 + m) * K + k0 + kc * 4;
            const float* srcL = Wl + (size_t)(m0 + m) * K + k0 + kc * 4;
            uint32_t doff = (uint32_t)(m * (A_STRIDE * 4) + kc * 16);
            cpasync16(base + doff, srcH);
            cpasync16(base + A_PLANE * 4 + doff, srcL);
        }
        // B plane: 512 chunks (16 k rows x 32 chunks of 4 n)
#pragma unroll
        for (int i = 0; i < 2; i++) {
            int c = tid + i * 256;
            int kr = c >> 5, nc = c & 31;
            cpasync16(base + 2 * A_PLANE * 4 + kr * (B_STRIDE * 4) + nc * 16,
                      Bb + (size_t)(k0 + kr) * N + n0 + nc * 4);
        }
        cp_commit();
    };

    float acc[4][4][4] = {};

    issue(0, 0);

    const int NIT = K / KT;   // 32
    for (int it = 0; it < NIT; ++it) {
        if (it + 1 < NIT) { issue((it + 1) * KT, (it + 1) & 1); cp_wait<1>(); }
        else              { cp_wait<0>(); }
        __syncthreads();

        const float* base = sm + (it & 1) * STAGE_F;
        const float* Ah = base;
        const float* Al = base + A_PLANE;
        const float* Bs = base + 2 * A_PLANE;

#pragma unroll
        for (int ks = 0; ks < KT; ks += 8) {
            const int r0 = ks + tig;
            const int r1 = ks + tig + 4;
            // B fragments: raw load + on-the-fly hi/lo split
            uint32_t bh0[4], bh1[4], bl0[4], bl1[4];
#pragma unroll
            for (int nf = 0; nf < 4; nf++) {
                int n = wn + nf * 8 + g;
                float v0 = Bs[r0 * B_STRIDE + n];
                float v1 = Bs[r1 * B_STRIDE + n];
                uint32_t h0 = f2tf32(v0);
                uint32_t h1 = f2tf32(v1);
                bh0[nf] = h0; bh1[nf] = h1;
                bl0[nf] = f2tf32(v0 - __uint_as_float(h0));
                bl1[nf] = f2tf32(v1 - __uint_as_float(h1));
            }
#pragma unroll
            for (int mf = 0; mf < 4; mf++) {
                int m = wm + mf * 16 + g;
                uint32_t a0h = __float_as_uint(Ah[m * A_STRIDE + r0]);
                uint32_t a1h = __float_as_uint(Ah[(m + 8) * A_STRIDE + r0]);
                uint32_t a2h = __float_as_uint(Ah[m * A_STRIDE + r0 + 4]);
                uint32_t a3h = __float_as_uint(Ah[(m + 8) * A_STRIDE + r0 + 4]);
                uint32_t a0l = __float_as_uint(Al[m * A_STRIDE + r0]);
                uint32_t a1l = __float_as_uint(Al[(m + 8) * A_STRIDE + r0]);
                uint32_t a2l = __float_as_uint(Al[m * A_STRIDE + r0 + 4]);
                uint32_t a3l = __float_as_uint(Al[(m + 8) * A_STRIDE + r0 + 4]);
#pragma unroll
                for (int nf = 0; nf < 4; nf++) {
                    mma_tf32(acc[mf][nf], a0h, a1h, a2h, a3h, bh0[nf], bh1[nf]);
                    mma_tf32(acc[mf][nf], a0h, a1h, a2h, a3h, bl0[nf], bl1[nf]);
                    mma_tf32(acc[mf][nf], a0l, a1l, a2l, a3l, bh0[nf], bh1[nf]);
                }
            }
        }
        __syncthreads();
    }

    // Epilogue
    const float* Xb = xep + (size_t)b * M * N;   // only deref'd when FUSE
    float* Cb = Cout + (size_t)b * M * N;
#pragma unroll
    for (int mf = 0; mf < 4; mf++) {
        int m = m0 + wm + mf * 16 + g;
        float bv0 = bias[m];
        float bv1 = bias[m + 8];
#pragma unroll
        for (int nf = 0; nf < 4; nf++) {
            int n = n0 + wn + nf * 8 + 2 * tig;
            float2 v0 = make_float2(acc[mf][nf][0] + bv0, acc[mf][nf][1] + bv0);
            float2 v1 = make_float2(acc[mf][nf][2] + bv1, acc[mf][nf][3] + bv1);
            if (FUSE) {
                float2 x0 = *(const float2*)&Xb[(size_t)m * N + n];
                float2 x1 = *(const float2*)&Xb[(size_t)(m + 8) * N + n];
                v0.x = fmaxf(0.f, v0.x * x0.x); v0.y = fmaxf(0.f, v0.y * x0.y);
                v1.x = fmaxf(0.f, v1.x * x1.x); v1.y = fmaxf(0.f, v1.y * x1.y);
            }
            *(float2*)&Cb[(size_t)m * N + n] = v0;
            *(float2*)&Cb[(size_t)(m + 8) * N + n] = v1;
        }
    }
}

// ---------------------------------------------------------------------------
// Sliding-window attention, 32-query tiles, 160-key band, V phase-staged
// into K's buffer. SMEM = 70.4 KB -> 3 CTAs/SM.
// ---------------------------------------------------------------------------
#define ATT_SMEM ((32 * 65 + 160 * 65 + 32 * 160) * 4)   // 70400 B

__global__ __launch_bounds__(256) void attn_kernel()
{
    const int t0 = blockIdx.x * 32;
    const int h  = blockIdx.y;
    const int b  = blockIdx.z;

    extern __shared__ float sm[];
    float* Qs = sm;                 // [32][65]
    float* Ks = Qs + 32 * 65;       // [160][65]   (later reused for V)
    float* S  = Ks + 160 * 65;      // [32][160]   (later reused for ctx^T)

    const int tid = threadIdx.x;
    const float* qbase = g_qkv + ((size_t)b * 3 * Ev + h * DHv) * Tv;
    const float* kbase = qbase + (size_t)Ev * Tv;
    const float* vbase = qbase + (size_t)2 * Ev * Tv;

    for (int idx = tid; idx < 32 * 64; idx += 256) {
        int d = idx >> 5, r = idx & 31;
        Qs[r * 65 + d] = qbase[(size_t)d * Tv + t0 + r];
    }
    for (int idx = tid; idx < 160 * 64; idx += 256) {
        int d = idx / 160, r = idx - d * 160;
        int t = t0 - WIN + r;
        Ks[r * 65 + d] = (t >= 0 && t < Tv) ? kbase[(size_t)d * Tv + t] : 0.f;
    }
    __syncthreads();

    const int tx = tid & 31;
    const int ty = tid >> 5;

    // S = Q @ K^T * scale + mask
    {
        float acc[4][5] = {};
#pragma unroll
        for (int kk = 0; kk < 64; kk++) {
            float rq[4], rk[5];
#pragma unroll
            for (int i = 0; i < 4; i++) rq[i] = Qs[(ty * 4 + i) * 65 + kk];
#pragma unroll
            for (int j = 0; j < 5; j++) rk[j] = Ks[(tx + j * 32) * 65 + kk];
#pragma unroll
            for (int i = 0; i < 4; i++)
#pragma unroll
                for (int j = 0; j < 5; j++)
                    acc[i][j] += rq[i] * rk[j];
        }
        const float scale = 0.125f;
#pragma unroll
        for (int i = 0; i < 4; i++) {
            int r = ty * 4 + i;
#pragma unroll
            for (int j = 0; j < 5; j++) {
                int c   = tx + j * 32;
                int gk  = t0 - WIN + c;
                int rel = r + WIN - c;
                bool valid = (rel >= -WIN) && (rel <= WIN) && (gk >= 0) && (gk < Tv);
                S[r * 160 + c] = valid ? acc[i][j] * scale : NEG_INF_F;
            }
        }
    }
    __syncthreads();

    for (int rr = 0; rr < 4; rr++) {
        int row = ty * 4 + rr;
        float v[5];
        float mx = -1e30f;
#pragma unroll
        for (int p = 0; p < 5; p++) {
            v[p] = S[row * 160 + tx + p * 32];
            mx = fmaxf(mx, v[p]);
        }
#pragma unroll
        for (int off = 16; off > 0; off >>= 1)
            mx = fmaxf(mx, __shfl_xor_sync(0xFFFFFFFFu, mx, off));
        float sum = 0.f;
#pragma unroll
        for (int p = 0; p < 5; p++) {
            v[p] = __expf(v[p] - mx);
            sum += v[p];
        }
#pragma unroll
        for (int off = 16; off > 0; off >>= 1)
            sum += __shfl_xor_sync(0xFFFFFFFFu, sum, off);
        float inv = 1.f / sum;
#pragma unroll
        for (int p = 0; p < 5; p++)
            S[row * 160 + tx + p * 32] = v[p] * inv;
    }
    __syncthreads();

    for (int idx = tid; idx < 160 * 64; idx += 256) {
        int d = idx / 160, r = idx - d * 160;
        int t = t0 - WIN + r;
        Ks[r * 65 + d] = (t >= 0 && t < Tv) ? vbase[(size_t)d * Tv + t] : 0.f;
    }
    __syncthreads();

    float acc2[4][2] = {};
    for (int kk = 0; kk < 160; kk++) {
        float rs[4], rv[2];
#pragma unroll
        for (int i = 0; i < 4; i++) rs[i] = S[(ty * 4 + i) * 160 + kk];
#pragma unroll
        for (int j = 0; j < 2; j++) rv[j] = Ks[kk * 65 + tx + j * 32];
#pragma unroll
        for (int i = 0; i < 4; i++)
#pragma unroll
            for (int j = 0; j < 2; j++)
                acc2[i][j] += rs[i] * rv[j];
    }
    __syncthreads();

#pragma unroll
    for (int i = 0; i < 4; i++)
#pragma unroll
        for (int j = 0; j < 2; j++)
            S[(tx + j * 32) * 33 + (ty * 4 + i)] = acc2[i][j];
    __syncthreads();

    float* cbase = g_ctx + ((size_t)b * Ev + h * DHv) * Tv;
    for (int idx = tid; idx < 64 * 32; idx += 256) {
        int d = idx >> 5, r = idx & 31;
        cbase[(size_t)d * Tv + t0 + r] = S[d * 33 + r];
    }
}

// ---------------------------------------------------------------------------
extern "C" void kernel_launch(void* const* d_in, const int* in_sizes, int n_in,
                              void* d_out, int out_size)
{
    const float* x     = (const float*)d_in[0];  // [B, E, T]
    const float* w_in  = (const float*)d_in[1];  // [3E, E]
    const float* b_in  = (const float*)d_in[2];  // [3E]
    const float* w_out = (const float*)d_in[3];  // [E, E]
    const float* b_out = (const float*)d_in[4];  // [E]
    float* out = (float*)d_out;                  // [B, E, T]

    void *qkvp = nullptr, *ctxp = nullptr, *whp = nullptr, *wlp = nullptr;
    cudaGetSymbolAddress(&qkvp, g_qkv);
    cudaGetSymbolAddress(&ctxp, g_ctx);
    cudaGetSymbolAddress(&whp, g_wh);
    cudaGetSymbolAddress(&wlp, g_wl);
    float* wh = (float*)whp;
    float* wl = (float*)wlp;

    cudaFuncSetAttribute(gemm_tc<false>,
                         cudaFuncAttributeMaxDynamicSharedMemorySize, GEMM_SMEM);
    cudaFuncSetAttribute(gemm_tc<true>,
                         cudaFuncAttributeMaxDynamicSharedMemorySize, GEMM_SMEM);
    cudaFuncSetAttribute(attn_kernel,
                         cudaFuncAttributeMaxDynamicSharedMemorySize, ATT_SMEM);

    // Prep: split weights into tf32 hi/lo planes
    split_w_kernel<<<(WIN_ELEMS + 255) / 256, 256>>>(w_in, wh, wl, WIN_ELEMS);
    split_w_kernel<<<(WOUT_ELEMS + 255) / 256, 256>>>(
        w_out, wh + WIN_ELEMS, wl + WIN_ELEMS, WOUT_ELEMS);

    // QKV projection: M=1536
    dim3 g1(Tv / 128, (3 * Ev) / 128, Bv);
    gemm_tc<false><<<g1, 256, GEMM_SMEM>>>(x, wh, wl, b_in, nullptr,
                                           (float*)qkvp, 3 * Ev);

    // Attention
    dim3 g2(Tv / 32, Hv, Bv);
    attn_kernel<<<g2, 256, ATT_SMEM>>>();

    // Output projection + fused epilogue: M=512
    dim3 g3(Tv / 128, Ev / 128, Bv);
    gemm_tc<true><<<g3, 256, GEMM_SMEM>>>((const float*)ctxp,
                                          wh + WIN_ELEMS, wl + WIN_ELEMS,
                                          b_out, x, out, Ev);
}

// round 9
// speedup vs baseline: 1.4108x; 1.0194x over previous
#include <cuda_runtime.h>
#include <cstdint>

// Problem constants
#define Bv 2
#define Ev 512
#define Tv 2048
#define Hv 8
#define DHv 64
#define WIN 64
#define NEG_INF_F (-1e9f)

// Scratch (allocation-free: __device__ globals)
__device__ float g_qkv[(size_t)Bv * 3 * Ev * Tv];  // [b][3E][t]
__device__ float g_ctx[(size_t)Bv * Ev * Tv];      // [b][E][t]
#define WIN_ELEMS (3 * Ev * Ev)
#define WOUT_ELEMS (Ev * Ev)
__device__ float g_wh[WIN_ELEMS + WOUT_ELEMS];
__device__ float g_wl[WIN_ELEMS + WOUT_ELEMS];

// ---------------------------------------------------------------------------
// TF32 helpers
// ---------------------------------------------------------------------------
__device__ __forceinline__ uint32_t f2tf32(float x) {
    uint32_t r;
    asm("cvt.rna.tf32.f32 %0, %1;" : "=r"(r) : "f"(x));
    return r;
}

__device__ __forceinline__ void mma_tf32(float c[4],
    uint32_t a0, uint32_t a1, uint32_t a2, uint32_t a3,
    uint32_t b0, uint32_t b1)
{
    asm volatile(
        "mma.sync.aligned.m16n8k8.row.col.f32.tf32.tf32.f32 "
        "{%0,%1,%2,%3}, {%4,%5,%6,%7}, {%8,%9}, {%0,%1,%2,%3};"
        : "+f"(c[0]), "+f"(c[1]), "+f"(c[2]), "+f"(c[3])
        : "r"(a0), "r"(a1), "r"(a2), "r"(a3), "r"(b0), "r"(b1));
}

__device__ __forceinline__ void cpasync16(uint32_t dst, const void* src) {
    asm volatile("cp.async.cg.shared.global [%0], [%1], 16;\n"
                 :: "r"(dst), "l"(src) : "memory");
}
template<int N>
__device__ __forceinline__ void cp_wait() {
    asm volatile("cp.async.wait_group %0;\n" :: "n"(N) : "memory");
}
__device__ __forceinline__ void cp_commit() {
    asm volatile("cp.async.commit_group;\n" ::: "memory");
}

// ---------------------------------------------------------------------------
// Weight split prep: Wh = tf32(W), Wl = tf32(W - Wh)
// ---------------------------------------------------------------------------
__global__ void split_w_kernel(const float* __restrict__ W,
                               float* __restrict__ Wh, float* __restrict__ Wl,
                               int n)
{
    int i = blockIdx.x * 256 + threadIdx.x;
    if (i < n) {
        float w = W[i];
        uint32_t hi = f2tf32(w);
        float hif = __uint_as_float(hi);
        Wh[i] = hif;
        Wl[i] = __uint_as_float(f2tf32(w - hif));
    }
}

// ---------------------------------------------------------------------------
// Tensor-core GEMM (3xTF32) — unchanged from R6
// ---------------------------------------------------------------------------
#define KT 16
#define A_PLANE 2560
#define A_STRIDE 20
#define B_PLANE 2176
#define B_STRIDE 136
#define STAGE_F (2 * A_PLANE + B_PLANE)
#define STAGE_B (STAGE_F * 4)
#define GEMM_SMEM (2 * STAGE_B)

template<bool FUSE>
__global__ __launch_bounds__(256, 2) void gemm_tc(
    const float* __restrict__ Bmat,
    const float* __restrict__ Wh,
    const float* __restrict__ Wl,
    const float* __restrict__ bias,
    const float* __restrict__ xep,
    float* __restrict__ Cout,
    int M)
{
    const int N = Tv, K = Ev;
    extern __shared__ float sm[];
    const uint32_t smem_base = (uint32_t)__cvta_generic_to_shared(sm);

    const int b  = blockIdx.z;
    const int m0 = blockIdx.y * 128;
    const int n0 = blockIdx.x * 128;
    const float* Bb = Bmat + (size_t)b * K * N;

    const int tid  = threadIdx.x;
    const int lane = tid & 31;
    const int warp = tid >> 5;
    const int wm = (warp >> 2) * 64;
    const int wn = (warp & 3) * 32;
    const int g  = lane >> 2;
    const int tig = lane & 3;

    auto issue = [&](int k0, int buf) {
        uint32_t base = smem_base + buf * STAGE_B;
#pragma unroll
        for (int i = 0; i < 2; i++) {
            int c = tid + i * 256;
            int m = c >> 2, kc = c & 3;
            const float* srcH = Wh + (size_t)(m0 + m) * K + k0 + kc * 4;
            const float* srcL = Wl + (size_t)(m0 + m) * K + k0 + kc * 4;
            uint32_t doff = (uint32_t)(m * (A_STRIDE * 4) + kc * 16);
            cpasync16(base + doff, srcH);
            cpasync16(base + A_PLANE * 4 + doff, srcL);
        }
#pragma unroll
        for (int i = 0; i < 2; i++) {
            int c = tid + i * 256;
            int kr = c >> 5, nc = c & 31;
            cpasync16(base + 2 * A_PLANE * 4 + kr * (B_STRIDE * 4) + nc * 16,
                      Bb + (size_t)(k0 + kr) * N + n0 + nc * 4);
        }
        cp_commit();
    };

    float acc[4][4][4] = {};

    issue(0, 0);

    const int NIT = K / KT;
    for (int it = 0; it < NIT; ++it) {
        if (it + 1 < NIT) { issue((it + 1) * KT, (it + 1) & 1); cp_wait<1>(); }
        else              { cp_wait<0>(); }
        __syncthreads();

        const float* base = sm + (it & 1) * STAGE_F;
        const float* Ah = base;
        const float* Al = base + A_PLANE;
        const float* Bs = base + 2 * A_PLANE;

#pragma unroll
        for (int ks = 0; ks < KT; ks += 8) {
            const int r0 = ks + tig;
            const int r1 = ks + tig + 4;
            uint32_t bh0[4], bh1[4], bl0[4], bl1[4];
#pragma unroll
            for (int nf = 0; nf < 4; nf++) {
                int n = wn + nf * 8 + g;
                float v0 = Bs[r0 * B_STRIDE + n];
                float v1 = Bs[r1 * B_STRIDE + n];
                uint32_t h0 = f2tf32(v0);
                uint32_t h1 = f2tf32(v1);
                bh0[nf] = h0; bh1[nf] = h1;
                bl0[nf] = f2tf32(v0 - __uint_as_float(h0));
                bl1[nf] = f2tf32(v1 - __uint_as_float(h1));
            }
#pragma unroll
            for (int mf = 0; mf < 4; mf++) {
                int m = wm + mf * 16 + g;
                uint32_t a0h = __float_as_uint(Ah[m * A_STRIDE + r0]);
                uint32_t a1h = __float_as_uint(Ah[(m + 8) * A_STRIDE + r0]);
                uint32_t a2h = __float_as_uint(Ah[m * A_STRIDE + r0 + 4]);
                uint32_t a3h = __float_as_uint(Ah[(m + 8) * A_STRIDE + r0 + 4]);
                uint32_t a0l = __float_as_uint(Al[m * A_STRIDE + r0]);
                uint32_t a1l = __float_as_uint(Al[(m + 8) * A_STRIDE + r0]);
                uint32_t a2l = __float_as_uint(Al[m * A_STRIDE + r0 + 4]);
                uint32_t a3l = __float_as_uint(Al[(m + 8) * A_STRIDE + r0 + 4]);
#pragma unroll
                for (int nf = 0; nf < 4; nf++) {
                    mma_tf32(acc[mf][nf], a0h, a1h, a2h, a3h, bh0[nf], bh1[nf]);
                    mma_tf32(acc[mf][nf], a0h, a1h, a2h, a3h, bl0[nf], bl1[nf]);
                    mma_tf32(acc[mf][nf], a0l, a1l, a2l, a3l, bh0[nf], bh1[nf]);
                }
            }
        }
        __syncthreads();
    }

    const float* Xb = xep + (size_t)b * M * N;
    float* Cb = Cout + (size_t)b * M * N;
#pragma unroll
    for (int mf = 0; mf < 4; mf++) {
        int m = m0 + wm + mf * 16 + g;
        float bv0 = bias[m];
        float bv1 = bias[m + 8];
#pragma unroll
        for (int nf = 0; nf < 4; nf++) {
            int n = n0 + wn + nf * 8 + 2 * tig;
            float2 v0 = make_float2(acc[mf][nf][0] + bv0, acc[mf][nf][1] + bv0);
            float2 v1 = make_float2(acc[mf][nf][2] + bv1, acc[mf][nf][3] + bv1);
            if (FUSE) {
                float2 x0 = *(const float2*)&Xb[(size_t)m * N + n];
                float2 x1 = *(const float2*)&Xb[(size_t)(m + 8) * N + n];
                v0.x = fmaxf(0.f, v0.x * x0.x); v0.y = fmaxf(0.f, v0.y * x0.y);
                v1.x = fmaxf(0.f, v1.x * x1.x); v1.y = fmaxf(0.f, v1.y * x1.y);
            }
            *(float2*)&Cb[(size_t)m * N + n] = v0;
            *(float2*)&Cb[(size_t)(m + 8) * N + n] = v1;
        }
    }
}

// ---------------------------------------------------------------------------
// Tensor-core sliding-window attention (3xTF32).
// 32-query tile, 160-key band. All tiles stored FEATURE-MAJOR [d][t] (no
// transposes: fragments are gathered element-wise from SMEM).
//   Phase 1: S(32x160) = Q·K^T  (M=q, N=key, K=d)
//   Softmax: P split hi/lo into Sh/Sl
//   Phase 2: ctx(32x64) = P·V   (M=q, N=d, K=key), V restaged into K buffer
// Strides chosen conflict-free: Q=72, K=168, V=164, S=164, ctxstage=36.
// ---------------------------------------------------------------------------
#define QS_STRIDE 72
#define KS_STRIDE 168
#define VS_STRIDE 164
#define S_STRIDE 164
#define QS_OFF 0
#define KS_OFF (64 * QS_STRIDE)                 // 4608
#define SH_OFF (KS_OFF + 64 * KS_STRIDE)        // 15360
#define SL_OFF (SH_OFF + 32 * S_STRIDE)         // 20608
#define ATT_FLOATS (SL_OFF + 32 * S_STRIDE)     // 25856
#define ATT_SMEM (ATT_FLOATS * 4)               // 103424 B

__global__ __launch_bounds__(256, 2) void attn_kernel()
{
    const int t0 = blockIdx.x * 32;
    const int h  = blockIdx.y;
    const int b  = blockIdx.z;

    extern __shared__ float sm[];
    float* Qs = sm + QS_OFF;   // [64 d][72]
    float* Ks = sm + KS_OFF;   // [64 d][168] (reused for V at stride 164)
    float* Sh = sm + SH_OFF;   // [32 q][164]
    float* Sl = sm + SL_OFF;   // [32 q][164]

    const int tid  = threadIdx.x;
    const int lane = tid & 31;
    const int warp = tid >> 5;
    const int g    = lane >> 2;
    const int tig  = lane & 3;
    const int q0   = (warp >> 2) * 16;   // phase-1/2 M offset

    const float* qbase = g_qkv + ((size_t)b * 3 * Ev + h * DHv) * Tv;
    const float* kbase = qbase + (size_t)Ev * Tv;
    const float* vbase = qbase + (size_t)2 * Ev * Tv;

    const int tb = t0 - WIN;
    const bool interior = (tb >= 0) && (tb + 160 <= Tv);

    // ---- Stage Q [64 d][32 t] and K [64 d][160 t], feature-major float4
    for (int idx = tid; idx < 64 * 8; idx += 256) {
        int d = idx >> 3, c = idx & 7;
        *(float4*)&Qs[d * QS_STRIDE + c * 4] =
            *(const float4*)&qbase[(size_t)d * Tv + t0 + c * 4];
    }
    if (interior) {
        for (int idx = tid; idx < 64 * 40; idx += 256) {
            int d = idx / 40, c = idx - d * 40;
            *(float4*)&Ks[d * KS_STRIDE + c * 4] =
                *(const float4*)&kbase[(size_t)d * Tv + tb + c * 4];
        }
    } else {
        for (int idx = tid; idx < 64 * 160; idx += 256) {
            int d = idx / 160, c = idx - d * 160;
            int t = tb + c;
            Ks[d * KS_STRIDE + c] =
                (t >= 0 && t < Tv) ? kbase[(size_t)d * Tv + t] : 0.f;
        }
    }
    __syncthreads();

    // ---- Phase 1: S = Q @ K^T (3xTF32). Warp tile: 16 q x 40 keys.
    {
        const int key0 = (warp & 3) * 40;
        float acc[5][4] = {};
#pragma unroll
        for (int ks = 0; ks < 64; ks += 8) {
            int ra = (ks + tig) * QS_STRIDE + q0 + g;
            int rb = ra + 4 * QS_STRIDE;
            float a0r = Qs[ra], a1r = Qs[ra + 8], a2r = Qs[rb], a3r = Qs[rb + 8];
            uint32_t a0h = f2tf32(a0r), a1h = f2tf32(a1r);
            uint32_t a2h = f2tf32(a2r), a3h = f2tf32(a3r);
            uint32_t a0l = f2tf32(a0r - __uint_as_float(a0h));
            uint32_t a1l = f2tf32(a1r - __uint_as_float(a1h));
            uint32_t a2l = f2tf32(a2r - __uint_as_float(a2h));
            uint32_t a3l = f2tf32(a3r - __uint_as_float(a3h));
            int kb0 = (ks + tig) * KS_STRIDE + key0 + g;
            int kb1 = kb0 + 4 * KS_STRIDE;
#pragma unroll
            for (int nf = 0; nf < 5; nf++) {
                float b0r = Ks[kb0 + nf * 8];
                float b1r = Ks[kb1 + nf * 8];
                uint32_t bh0 = f2tf32(b0r), bh1 = f2tf32(b1r);
                uint32_t bl0 = f2tf32(b0r - __uint_as_float(bh0));
                uint32_t bl1 = f2tf32(b1r - __uint_as_float(bh1));
                mma_tf32(acc[nf], a0h, a1h, a2h, a3h, bh0, bh1);
                mma_tf32(acc[nf], a0h, a1h, a2h, a3h, bl0, bl1);
                mma_tf32(acc[nf], a0l, a1l, a2l, a3l, bh0, bh1);
            }
        }
        // scale + mask + write scores
#pragma unroll
        for (int nf = 0; nf < 5; nf++) {
            int col0 = key0 + nf * 8 + 2 * tig;
#pragma unroll
            for (int e = 0; e < 4; e++) {
                int r = q0 + g + ((e >> 1) * 8);
                int c = col0 + (e & 1);
                int gk = tb + c;
                int rel = r + WIN - c;              // gq - gk
                bool valid = (rel >= -WIN) && (rel <= WIN) && (gk >= 0) && (gk < Tv);
                Sh[r * S_STRIDE + c] = valid ? acc[nf][e] * 0.125f : NEG_INF_F;
            }
        }
    }
    __syncthreads();

    // ---- Softmax (each warp: 4 rows) + split P into hi/lo planes
    for (int rr = 0; rr < 4; rr++) {
        int row = warp * 4 + rr;
        float v[5];
        float mx = -1e30f;
#pragma unroll
        for (int p = 0; p < 5; p++) {
            v[p] = Sh[row * S_STRIDE + lane + p * 32];
            mx = fmaxf(mx, v[p]);
        }
#pragma unroll
        for (int off = 16; off > 0; off >>= 1)
            mx = fmaxf(mx, __shfl_xor_sync(0xFFFFFFFFu, mx, off));
        float sum = 0.f;
#pragma unroll
        for (int p = 0; p < 5; p++) {
            v[p] = __expf(v[p] - mx);
            sum += v[p];
        }
#pragma unroll
        for (int off = 16; off > 0; off >>= 1)
            sum += __shfl_xor_sync(0xFFFFFFFFu, sum, off);
        float inv = 1.f / sum;
#pragma unroll
        for (int p = 0; p < 5; p++) {
            float pv = v[p] * inv;
            uint32_t ph = f2tf32(pv);
            Sh[row * S_STRIDE + lane + p * 32] = __uint_as_float(ph);
            Sl[row * S_STRIDE + lane + p * 32] =
                __uint_as_float(f2tf32(pv - __uint_as_float(ph)));
        }
    }

    // ---- Restage V into K buffer (stride 164), feature-major
    if (interior) {
        for (int idx = tid; idx < 64 * 40; idx += 256) {
            int d = idx / 40, c = idx - d * 40;
            *(float4*)&Ks[d * VS_STRIDE + c * 4] =
                *(const float4*)&vbase[(size_t)d * Tv + tb + c * 4];
        }
    } else {
        for (int idx = tid; idx < 64 * 160; idx += 256) {
            int d = idx / 160, c = idx - d * 160;
            int t = tb + c;
            Ks[d * VS_STRIDE + c] =
                (t >= 0 && t < Tv) ? vbase[(size_t)d * Tv + t] : 0.f;
        }
    }
    __syncthreads();

    // ---- Phase 2: ctx = P @ V (3xTF32). Warp tile: 16 q x 16 d.
    {
        const int d0 = (warp & 3) * 16;
        float acc2[2][4] = {};
#pragma unroll 4
        for (int ks = 0; ks < 160; ks += 8) {
            int pa = (q0 + g) * S_STRIDE + ks + tig;
            int pb = pa + 8 * S_STRIDE;
            uint32_t a0h = __float_as_uint(Sh[pa]);
            uint32_t a1h = __float_as_uint(Sh[pb]);
            uint32_t a2h = __float_as_uint(Sh[pa + 4]);
            uint32_t a3h = __float_as_uint(Sh[pb + 4]);
            uint32_t a0l = __float_as_uint(Sl[pa]);
            uint32_t a1l = __float_as_uint(Sl[pb]);
            uint32_t a2l = __float_as_uint(Sl[pa + 4]);
            uint32_t a3l = __float_as_uint(Sl[pb + 4]);
#pragma unroll
            for (int nf = 0; nf < 2; nf++) {
                int vrow = (d0 + nf * 8 + g) * VS_STRIDE + ks + tig;
                float b0r = Ks[vrow];
                float b1r = Ks[vrow + 4];
                uint32_t bh0 = f2tf32(b0r), bh1 = f2tf32(b1r);
                uint32_t bl0 = f2tf32(b0r - __uint_as_float(bh0));
                uint32_t bl1 = f2tf32(b1r - __uint_as_float(bh1));
                mma_tf32(acc2[nf], a0h, a1h, a2h, a3h, bh0, bh1);
                mma_tf32(acc2[nf], a0h, a1h, a2h, a3h, bl0, bl1);
                mma_tf32(acc2[nf], a0l, a1l, a2l, a3l, bh0, bh1);
            }
        }
        __syncthreads();   // all reads of Sh/Sl/Ks done; Qs reads long done

        // Stage ctx [64 d][32 q] into Qs (stride 36), conflict-free
#pragma unroll
        for (int nf = 0; nf < 2; nf++) {
            int dcol = d0 + nf * 8 + 2 * tig;
            Qs[dcol * 36 + q0 + g]           = acc2[nf][0];
            Qs[(dcol + 1) * 36 + q0 + g]     = acc2[nf][1];
            Qs[dcol * 36 + q0 + g + 8]       = acc2[nf][2];
            Qs[(dcol + 1) * 36 + q0 + g + 8] = acc2[nf][3];
        }
    }
    __syncthreads();

    // ---- Coalesced output: g_ctx[b][h*64+d][t0+q]
    float* cbase = g_ctx + ((size_t)b * Ev + h * DHv) * Tv;
    for (int idx = tid; idx < 64 * 32; idx += 256) {
        int d = idx >> 5, q = idx & 31;
        cbase[(size_t)d * Tv + t0 + q] = Qs[d * 36 + q];
    }
}

// ---------------------------------------------------------------------------
extern "C" void kernel_launch(void* const* d_in, const int* in_sizes, int n_in,
                              void* d_out, int out_size)
{
    const float* x     = (const float*)d_in[0];  // [B, E, T]
    const float* w_in  = (const float*)d_in[1];  // [3E, E]
    const float* b_in  = (const float*)d_in[2];  // [3E]
    const float* w_out = (const float*)d_in[3];  // [E, E]
    const float* b_out = (const float*)d_in[4];  // [E]
    float* out = (float*)d_out;                  // [B, E, T]

    void *qkvp = nullptr, *ctxp = nullptr, *whp = nullptr, *wlp = nullptr;
    cudaGetSymbolAddress(&qkvp, g_qkv);
    cudaGetSymbolAddress(&ctxp, g_ctx);
    cudaGetSymbolAddress(&whp, g_wh);
    cudaGetSymbolAddress(&wlp, g_wl);
    float* wh = (float*)whp;
    float* wl = (float*)wlp;

    cudaFuncSetAttribute(gemm_tc<false>,
                         cudaFuncAttributeMaxDynamicSharedMemorySize, GEMM_SMEM);
    cudaFuncSetAttribute(gemm_tc<true>,
                         cudaFuncAttributeMaxDynamicSharedMemorySize, GEMM_SMEM);
    cudaFuncSetAttribute(attn_kernel,
                         cudaFuncAttributeMaxDynamicSharedMemorySize, ATT_SMEM);

    // Prep: split weights into tf32 hi/lo planes
    split_w_kernel<<<(WIN_ELEMS + 255) / 256, 256>>>(w_in, wh, wl, WIN_ELEMS);
    split_w_kernel<<<(WOUT_ELEMS + 255) / 256, 256>>>(
        w_out, wh + WIN_ELEMS, wl + WIN_ELEMS, WOUT_ELEMS);

    // QKV projection: M=1536
    dim3 g1(Tv / 128, (3 * Ev) / 128, Bv);
    gemm_tc<false><<<g1, 256, GEMM_SMEM>>>(x, wh, wl, b_in, nullptr,
                                           (float*)qkvp, 3 * Ev);

    // Attention (tensor-core)
    dim3 g2(Tv / 32, Hv, Bv);
    attn_kernel<<<g2, 256, ATT_SMEM>>>();

    // Output projection + fused epilogue: M=512
    dim3 g3(Tv / 128, Ev / 128, Bv);
    gemm_tc<true><<<g3, 256, GEMM_SMEM>>>((const float*)ctxp,
                                          wh + WIN_ELEMS, wl + WIN_ELEMS,
                                          b_out, x, out, Ev);
}